// round 14
// baseline (speedup 1.0000x reference)
#include <cuda_runtime.h>
#include <cuda_fp16.h>
#include <cstdint>

#define NN 20000
#define EE 320000
#define DD 128
#define KK 8
#define HH 64
#define KH 512   // K*H

// ---------------- scratch (static device arrays, zero-initialized) ----------
__device__ __half g_meanh[(size_t)EE * DD];        // 82 MB mean features (fp16)
__device__ float g_ex[(size_t)EE * KK];            // exp(logits)
__device__ float g_er[(size_t)NN * KK];            // node_feat @ W_r^T
__device__ float g_W2[KK * DD];                    // [k][d] reduced weights
__device__ float g_S[(size_t)NN * KK * DD];        // aggregated, normalized
__device__ int   g_cnt[NN];                        // zero at entry (scan re-zeroes)
__device__ int   g_off[NN + 1];
__device__ int   g_cur[NN];
__device__ int   g_list[EE];

__device__ __forceinline__ float to_tf32(float x) {
    float r;
    asm("cvt.rna.tf32.f32 %0, %1;" : "=f"(r) : "f"(x));
    return r;
}
__device__ __forceinline__ void mma_tf32(float* c, const uint32_t* a, const uint32_t* b) {
    asm volatile(
        "mma.sync.aligned.m16n8k8.row.col.f32.tf32.tf32.f32 "
        "{%0,%1,%2,%3}, {%4,%5,%6,%7}, {%8,%9}, {%0,%1,%2,%3};"
        : "+f"(c[0]), "+f"(c[1]), "+f"(c[2]), "+f"(c[3])
        : "r"(a[0]), "r"(a[1]), "r"(a[2]), "r"(a[3]), "r"(b[0]), "r"(b[1]));
}

// ---------------- K1: W2 + er + histogram (all independent) ------------------
__global__ __launch_bounds__(256) void prep_hist_kernel(
    const float* __restrict__ nf, const float* __restrict__ Wr,
    const float* __restrict__ W_enc, const float* __restrict__ attn_l,
    const int* __restrict__ dst) {
    int b = blockIdx.x;
    int t = threadIdx.x;
    if (b < 1250) {                       // histogram part
        int e = b * 256 + t;
        atomicAdd(&g_cnt[dst[e]], 1);
    }
    if (b < 4) {
        int idx = b * 256 + t;
        if (idx < KK * DD) {
            int d = idx >> 3, k = idx & 7;
            float s = 0.0f;
#pragma unroll 8
            for (int h = 0; h < HH; h++)
                s += W_enc[(size_t)d * KH + k * HH + h] * attn_l[k * HH + h];
            g_W2[k * DD + d] = s;
        }
    } else {
        int warp = (b - 4) * 8 + (t >> 5);
        int lane = t & 31;
        if (warp >= NN) return;
        float4 x = *(const float4*)(nf + (size_t)warp * DD + lane * 4);
#pragma unroll
        for (int k = 0; k < KK; k++) {
            float4 w = *(const float4*)(Wr + (size_t)k * DD + lane * 4);
            float p = x.x * w.x + x.y * w.y + x.z * w.z + x.w * w.w;
#pragma unroll
            for (int off = 16; off > 0; off >>= 1)
                p += __shfl_xor_sync(0xffffffffu, p, off);
            if (lane == 0) g_er[(size_t)warp * KK + k] = p;
        }
    }
}

// ---------------- K2: scan (single block) ------------------------------------
__global__ void scan_kernel() {   // 1024 threads, 20 counts each
    __shared__ int part[1024];
    int t = threadIdx.x;
    int base = t * 20;
    int loc[20];
    int s = 0;
#pragma unroll
    for (int i = 0; i < 20; i++) {
        int idx = base + i;
        int c = (idx < NN) ? g_cnt[idx] : 0;
        loc[i] = s;
        s += c;
    }
    part[t] = s;
    __syncthreads();
    for (int off = 1; off < 1024; off <<= 1) {
        int v = (t >= off) ? part[t - off] : 0;
        __syncthreads();
        part[t] += v;
        __syncthreads();
    }
    int excl = (t == 0) ? 0 : part[t - 1];
#pragma unroll
    for (int i = 0; i < 20; i++) {
        int idx = base + i;
        if (idx < NN) {
            g_off[idx] = excl + loc[i];
            g_cur[idx] = excl + loc[i];
            g_cnt[idx] = 0;            // leave zeroed for next launch call
        }
    }
    if (t == 1023) g_off[NN] = part[1023];
}

// ---------------- K3: mean + logits + exp, plus CSR fill ---------------------
__global__ __launch_bounds__(256) void mean_logits_fill_kernel(
    const float* __restrict__ ef, const int* __restrict__ dst) {
    __shared__ float w2s[KK * DD];
    int t = threadIdx.x;

    if (blockIdx.x < 1250) {              // fill part (needs scan done: K2)
        int e = blockIdx.x * 256 + t;
        int p = atomicAdd(&g_cur[dst[e]], 1);
        g_list[p] = e;
    }

    for (int i = t; i < KK * DD; i += 256) w2s[i] = g_W2[i];
    __syncthreads();

    int warp = blockIdx.x * 8 + (t >> 5);   // EE/8 blocks, always full
    int lane = t & 31;

    size_t base = (size_t)warp * 3 * DD + lane * 4;
    float4 a = *(const float4*)(ef + base);
    float4 b = *(const float4*)(ef + base + DD);
    float4 c = *(const float4*)(ef + base + 2 * DD);
    const float s = 1.0f / 3.0f;
    float4 m;
    m.x = (a.x + b.x + c.x) * s;
    m.y = (a.y + b.y + c.y) * s;
    m.z = (a.z + b.z + c.z) * s;
    m.w = (a.w + b.w + c.w) * s;

    // fp16 store (logits below use exact fp32 m)
    __half2 h0 = __floats2half2_rn(m.x, m.y);
    __half2 h1 = __floats2half2_rn(m.z, m.w);
    uint2 u;
    u.x = *reinterpret_cast<uint32_t*>(&h0);
    u.y = *reinterpret_cast<uint32_t*>(&h1);
    *(uint2*)(g_meanh + (size_t)warp * DD + lane * 4) = u;

    float pk[KK];
#pragma unroll
    for (int k = 0; k < KK; k++) {
        float4 w = *(const float4*)(w2s + k * DD + lane * 4);
        pk[k] = m.x * w.x + m.y * w.y + m.z * w.z + m.w * w.w;
    }
    // fold reduction: 8 values -> 1 value/lane in 9 SHFLs
    float v4[4];
#pragma unroll
    for (int i = 0; i < 4; i++) {
        float send = (lane & 16) ? pk[i] : pk[i + 4];
        float recv = __shfl_xor_sync(0xffffffffu, send, 16);
        v4[i] = ((lane & 16) ? pk[i + 4] : pk[i]) + recv;
    }
    float v2[2];
#pragma unroll
    for (int i = 0; i < 2; i++) {
        float send = (lane & 8) ? v4[i] : v4[i + 2];
        float recv = __shfl_xor_sync(0xffffffffu, send, 8);
        v2[i] = ((lane & 8) ? v4[i + 2] : v4[i]) + recv;
    }
    {
        float send = (lane & 4) ? v2[0] : v2[1];
        float recv = __shfl_xor_sync(0xffffffffu, send, 4);
        v2[0] = ((lane & 4) ? v2[1] : v2[0]) + recv;
    }
    v2[0] += __shfl_xor_sync(0xffffffffu, v2[0], 1);
    v2[0] += __shfl_xor_sync(0xffffffffu, v2[0], 2);

    int d = dst[warp];
    if ((lane & 3) == 0) {
        int k = lane >> 2;
        float v = v2[0] + g_er[(size_t)d * KK + k];
        v = (v > 0.0f) ? v : 0.01f * v;
        g_ex[(size_t)warp * KK + k] = expf(v);
    }
}

// ---------------- K4: per-node aggregate — ONE WARP PER NODE -----------------
// lane owns 4 dims for all 8 heads; per edge: 8B row slice + 32B ex broadcast.
// No smem, no barriers, each mean row read exactly once.
__global__ __launch_bounds__(256) void aggregate_kernel() {
    int n = (blockIdx.x << 3) + (threadIdx.x >> 5);  // NN/8 blocks, exact
    int lane = threadIdx.x & 31;
    int beg = g_off[n], end = g_off[n + 1];

    float acc[KK][4];
#pragma unroll
    for (int k = 0; k < KK; k++)
#pragma unroll
        for (int j = 0; j < 4; j++) acc[k][j] = 0.0f;
    float exsum[KK];
#pragma unroll
    for (int k = 0; k < KK; k++) exsum[k] = 0.0f;

#pragma unroll 2
    for (int p = beg; p < end; p++) {
        int e = g_list[p];
        uint2 r = *(const uint2*)(g_meanh + (size_t)e * DD + lane * 4);
        float4 ex0 = *(const float4*)(g_ex + (size_t)e * KK);      // uniform addr
        float4 ex1 = *(const float4*)(g_ex + (size_t)e * KK + 4);  // uniform addr
        __half2 h0 = *reinterpret_cast<__half2*>(&r.x);
        __half2 h1 = *reinterpret_cast<__half2*>(&r.y);
        float2 f0 = __half22float2(h0);
        float2 f1 = __half22float2(h1);
        float ev[KK] = {ex0.x, ex0.y, ex0.z, ex0.w, ex1.x, ex1.y, ex1.z, ex1.w};
#pragma unroll
        for (int k = 0; k < KK; k++) {
            acc[k][0] += ev[k] * f0.x;
            acc[k][1] += ev[k] * f0.y;
            acc[k][2] += ev[k] * f1.x;
            acc[k][3] += ev[k] * f1.y;
            exsum[k] += ev[k];
        }
    }

#pragma unroll
    for (int k = 0; k < KK; k++) {
        float scale = (exsum[k] > 0.0f) ? (1.0f / exsum[k]) : 0.0f;
        *(float4*)(g_S + ((size_t)n * KK + k) * DD + lane * 4) =
            make_float4(acc[k][0] * scale, acc[k][1] * scale,
                        acc[k][2] * scale, acc[k][3] * scale);
    }
}

// ---------------- K5: out_gemm via tf32 mma.sync -----------------------------
// block = (64 nodes, 1 head): C(64x64) = S_tile(64x128) @ W_tile(128x64)
#define AP 132   // A smem row stride
#define BP 68    // B smem row stride
#define SMEM_G ((64 * AP + DD * BP) * 4)
__global__ __launch_bounds__(256) void out_gemm_kernel(
    const float* __restrict__ W_enc, float* __restrict__ out) {
    extern __shared__ float smg[];
    float* As = smg;              // [64][AP]
    float* Bs = smg + 64 * AP;    // [DD][BP]

    int t = threadIdx.x;
    int n0 = blockIdx.x * 64;
    int k = blockIdx.y;

#pragma unroll
    for (int i = 0; i < 8; i++) {
        int idx = i * 256 + t;         // 2048 float4s
        int r = idx >> 5, c4 = idx & 31;
        int n = n0 + r;
        float4 v = (n < NN)
            ? *(const float4*)(g_S + ((size_t)n * KK + k) * DD + c4 * 4)
            : make_float4(0.f, 0.f, 0.f, 0.f);
        v.x = to_tf32(v.x); v.y = to_tf32(v.y);
        v.z = to_tf32(v.z); v.w = to_tf32(v.w);
        *(float4*)(As + r * AP + c4 * 4) = v;
    }
#pragma unroll
    for (int i = 0; i < 8; i++) {
        int idx = i * 256 + t;         // 2048 float4s
        int d = idx >> 4, h4 = idx & 15;
        float4 v = *(const float4*)(W_enc + (size_t)d * KH + k * HH + h4 * 4);
        v.x = to_tf32(v.x); v.y = to_tf32(v.y);
        v.z = to_tf32(v.z); v.w = to_tf32(v.w);
        *(float4*)(Bs + d * BP + h4 * 4) = v;
    }
    __syncthreads();

    int w = t >> 5, lane = t & 31;
    int g = lane >> 2, tig = lane & 3;
    int warp_m = w >> 2, warp_n = w & 3;

    float c[2][2][4];
#pragma unroll
    for (int mi = 0; mi < 2; mi++)
#pragma unroll
        for (int j = 0; j < 2; j++)
#pragma unroll
            for (int q = 0; q < 4; q++) c[mi][j][q] = 0.0f;

    const uint32_t* Au = (const uint32_t*)As;
    const uint32_t* Bu = (const uint32_t*)Bs;

#pragma unroll 4
    for (int kc = 0; kc < 16; kc++) {
        int k0 = kc * 8;
        uint32_t a[2][4];
#pragma unroll
        for (int mi = 0; mi < 2; mi++) {
            int rb = warp_m * 32 + mi * 16;
            a[mi][0] = Au[(rb + g) * AP + k0 + tig];
            a[mi][1] = Au[(rb + g + 8) * AP + k0 + tig];
            a[mi][2] = Au[(rb + g) * AP + k0 + tig + 4];
            a[mi][3] = Au[(rb + g + 8) * AP + k0 + tig + 4];
        }
        uint32_t b[2][2];
#pragma unroll
        for (int j = 0; j < 2; j++) {
            int nb = warp_n * 16 + j * 8 + g;
            b[j][0] = Bu[(k0 + tig) * BP + nb];
            b[j][1] = Bu[(k0 + tig + 4) * BP + nb];
        }
#pragma unroll
        for (int mi = 0; mi < 2; mi++)
#pragma unroll
            for (int j = 0; j < 2; j++) mma_tf32(c[mi][j], a[mi], b[j]);
    }

#pragma unroll
    for (int mi = 0; mi < 2; mi++) {
        int row0 = n0 + warp_m * 32 + mi * 16 + g;
#pragma unroll
        for (int j = 0; j < 2; j++) {
            int col = k * HH + warp_n * 16 + j * 8 + 2 * tig;
            if (row0 < NN)
                *(float2*)(out + (size_t)row0 * KH + col) =
                    make_float2(c[mi][j][0], c[mi][j][1]);
            if (row0 + 8 < NN)
                *(float2*)(out + (size_t)(row0 + 8) * KH + col) =
                    make_float2(c[mi][j][2], c[mi][j][3]);
        }
    }
}

// ---------------- launch -----------------------------------------------------
extern "C" void kernel_launch(void* const* d_in, const int* in_sizes, int n_in,
                              void* d_out, int out_size) {
    const float* node_feat = (const float*)d_in[0];   // (N,128)
    const float* edge_feat = (const float*)d_in[1];   // (E,3,128)
    const float* W_enc     = (const float*)d_in[2];   // (128,512)
    const float* attn_l    = (const float*)d_in[3];   // (1,8,64)
    const float* W_r       = (const float*)d_in[4];   // (8,128)
    const int*   dst       = (const int*)d_in[5];     // (E,)
    float* out = (float*)d_out;                       // (N,8,64)

    cudaFuncSetAttribute(out_gemm_kernel,
                         cudaFuncAttributeMaxDynamicSharedMemorySize, SMEM_G);

    prep_hist_kernel<<<2504, 256>>>(node_feat, W_r, W_enc, attn_l, dst);
    scan_kernel<<<1, 1024>>>();
    mean_logits_fill_kernel<<<EE / 8, 256>>>(edge_feat, dst);
    aggregate_kernel<<<NN / 8, 256>>>();
    out_gemm_kernel<<<dim3((NN + 63) / 64, KK), 256, SMEM_G>>>(W_enc, out);
}

// round 15
// speedup vs baseline: 1.0401x; 1.0401x over previous
#include <cuda_runtime.h>
#include <cuda_fp16.h>
#include <cstdint>

#define NN 20000
#define EE 320000
#define DD 128
#define KK 8
#define HH 64
#define KH 512   // K*H

// ---------------- scratch (static device arrays, zero-initialized) ----------
__device__ __half g_meanh[(size_t)EE * DD];        // 82 MB mean features (fp16)
__device__ float g_ex[(size_t)EE * KK];            // exp(logits)
__device__ float g_er[(size_t)NN * KK];            // node_feat @ W_r^T
__device__ float g_W2[KK * DD];                    // [k][d] reduced weights
__device__ __half g_Sh[(size_t)NN * KK * DD];      // aggregated, normalized (fp16)
__device__ int   g_cnt[NN];                        // zero at entry (scan re-zeroes)
__device__ int   g_off[NN + 1];
__device__ int   g_cur[NN];
__device__ int   g_list[EE];

__device__ __forceinline__ float to_tf32(float x) {
    float r;
    asm("cvt.rna.tf32.f32 %0, %1;" : "=f"(r) : "f"(x));
    return r;
}
__device__ __forceinline__ void mma_tf32(float* c, const uint32_t* a, const uint32_t* b) {
    asm volatile(
        "mma.sync.aligned.m16n8k8.row.col.f32.tf32.tf32.f32 "
        "{%0,%1,%2,%3}, {%4,%5,%6,%7}, {%8,%9}, {%0,%1,%2,%3};"
        : "+f"(c[0]), "+f"(c[1]), "+f"(c[2]), "+f"(c[3])
        : "r"(a[0]), "r"(a[1]), "r"(a[2]), "r"(a[3]), "r"(b[0]), "r"(b[1]));
}

// ---------------- K1: W2 + er + histogram (all independent) ------------------
__global__ __launch_bounds__(256) void prep_hist_kernel(
    const float* __restrict__ nf, const float* __restrict__ Wr,
    const float* __restrict__ W_enc, const float* __restrict__ attn_l,
    const int* __restrict__ dst) {
    int b = blockIdx.x;
    int t = threadIdx.x;
    if (b < 1250) {                       // histogram part
        int e = b * 256 + t;
        atomicAdd(&g_cnt[dst[e]], 1);
    }
    if (b < 4) {
        int idx = b * 256 + t;
        if (idx < KK * DD) {
            int d = idx >> 3, k = idx & 7;
            float s = 0.0f;
#pragma unroll 8
            for (int h = 0; h < HH; h++)
                s += W_enc[(size_t)d * KH + k * HH + h] * attn_l[k * HH + h];
            g_W2[k * DD + d] = s;
        }
    } else {
        int warp = (b - 4) * 8 + (t >> 5);
        int lane = t & 31;
        if (warp >= NN) return;
        float4 x = *(const float4*)(nf + (size_t)warp * DD + lane * 4);
#pragma unroll
        for (int k = 0; k < KK; k++) {
            float4 w = *(const float4*)(Wr + (size_t)k * DD + lane * 4);
            float p = x.x * w.x + x.y * w.y + x.z * w.z + x.w * w.w;
#pragma unroll
            for (int off = 16; off > 0; off >>= 1)
                p += __shfl_xor_sync(0xffffffffu, p, off);
            if (lane == 0) g_er[(size_t)warp * KK + k] = p;
        }
    }
}

// ---------------- K2: scan (single block) ------------------------------------
__global__ void scan_kernel() {   // 1024 threads, 20 counts each
    __shared__ int part[1024];
    int t = threadIdx.x;
    int base = t * 20;
    int loc[20];
    int s = 0;
#pragma unroll
    for (int i = 0; i < 20; i++) {
        int idx = base + i;
        int c = (idx < NN) ? g_cnt[idx] : 0;
        loc[i] = s;
        s += c;
    }
    part[t] = s;
    __syncthreads();
    for (int off = 1; off < 1024; off <<= 1) {
        int v = (t >= off) ? part[t - off] : 0;
        __syncthreads();
        part[t] += v;
        __syncthreads();
    }
    int excl = (t == 0) ? 0 : part[t - 1];
#pragma unroll
    for (int i = 0; i < 20; i++) {
        int idx = base + i;
        if (idx < NN) {
            g_off[idx] = excl + loc[i];
            g_cur[idx] = excl + loc[i];
            g_cnt[idx] = 0;            // leave zeroed for next launch call
        }
    }
    if (t == 1023) g_off[NN] = part[1023];
}

// ---------------- K3: mean + logits + exp, plus CSR fill ---------------------
__global__ __launch_bounds__(256) void mean_logits_fill_kernel(
    const float* __restrict__ ef, const int* __restrict__ dst) {
    __shared__ float w2s[KK * DD];
    int t = threadIdx.x;

    if (blockIdx.x < 1250) {              // fill part (needs scan done: K2)
        int e = blockIdx.x * 256 + t;
        int p = atomicAdd(&g_cur[dst[e]], 1);
        g_list[p] = e;
    }

    for (int i = t; i < KK * DD; i += 256) w2s[i] = g_W2[i];
    __syncthreads();

    int warp = blockIdx.x * 8 + (t >> 5);   // EE/8 blocks, always full
    int lane = t & 31;

    size_t base = (size_t)warp * 3 * DD + lane * 4;
    float4 a = *(const float4*)(ef + base);
    float4 b = *(const float4*)(ef + base + DD);
    float4 c = *(const float4*)(ef + base + 2 * DD);
    const float s = 1.0f / 3.0f;
    float4 m;
    m.x = (a.x + b.x + c.x) * s;
    m.y = (a.y + b.y + c.y) * s;
    m.z = (a.z + b.z + c.z) * s;
    m.w = (a.w + b.w + c.w) * s;

    // fp16 store (logits below use exact fp32 m)
    __half2 h0 = __floats2half2_rn(m.x, m.y);
    __half2 h1 = __floats2half2_rn(m.z, m.w);
    uint2 u;
    u.x = *reinterpret_cast<uint32_t*>(&h0);
    u.y = *reinterpret_cast<uint32_t*>(&h1);
    *(uint2*)(g_meanh + (size_t)warp * DD + lane * 4) = u;

    float pk[KK];
#pragma unroll
    for (int k = 0; k < KK; k++) {
        float4 w = *(const float4*)(w2s + k * DD + lane * 4);
        pk[k] = m.x * w.x + m.y * w.y + m.z * w.z + m.w * w.w;
    }
    // fold reduction: 8 values -> 1 value/lane in 9 SHFLs
    float v4[4];
#pragma unroll
    for (int i = 0; i < 4; i++) {
        float send = (lane & 16) ? pk[i] : pk[i + 4];
        float recv = __shfl_xor_sync(0xffffffffu, send, 16);
        v4[i] = ((lane & 16) ? pk[i + 4] : pk[i]) + recv;
    }
    float v2[2];
#pragma unroll
    for (int i = 0; i < 2; i++) {
        float send = (lane & 8) ? v4[i] : v4[i + 2];
        float recv = __shfl_xor_sync(0xffffffffu, send, 8);
        v2[i] = ((lane & 8) ? v4[i + 2] : v4[i]) + recv;
    }
    {
        float send = (lane & 4) ? v2[0] : v2[1];
        float recv = __shfl_xor_sync(0xffffffffu, send, 4);
        v2[0] = ((lane & 4) ? v2[1] : v2[0]) + recv;
    }
    v2[0] += __shfl_xor_sync(0xffffffffu, v2[0], 1);
    v2[0] += __shfl_xor_sync(0xffffffffu, v2[0], 2);

    int d = dst[warp];
    if ((lane & 3) == 0) {
        int k = lane >> 2;
        float v = v2[0] + g_er[(size_t)d * KK + k];
        v = (v > 0.0f) ? v : 0.01f * v;
        g_ex[(size_t)warp * KK + k] = expf(v);
    }
}

// ---------------- K4: per-node gather-aggregate (staged; fp16 S output) ------
#define BATCH 32
__global__ __launch_bounds__(256) void aggregate_kernel() {
    __shared__ __half msh[BATCH][DD];    // 8 KB
    __shared__ float exs[BATCH][KK];     // 1 KB
    int n = blockIdx.x;
    int t = threadIdx.x;
    int k = t >> 5, d4 = t & 31;
    int beg = g_off[n], end = g_off[n + 1];

    float4 acc = make_float4(0.f, 0.f, 0.f, 0.f);
    float exsum = 0.0f;

    for (int p0 = beg; p0 < end; p0 += BATCH) {
        int nb = end - p0;
        if (nb > BATCH) nb = BATCH;
        for (int i = t; i < nb * 16; i += 256) {
            int j = i >> 4, c8 = i & 15;
            int e = g_list[p0 + j];
            *(uint4*)&msh[j][c8 * 8] =
                *(const uint4*)(g_meanh + (size_t)e * DD + c8 * 8);
        }
        if (t < nb * KK) {
            int j = t >> 3, kk = t & 7;
            int e = g_list[p0 + j];
            exs[j][kk] = g_ex[(size_t)e * KK + kk];
        }
        __syncthreads();
#pragma unroll 4
        for (int j = 0; j < nb; j++) {
            float ev = exs[j][k];
            uint2 r = *(const uint2*)&msh[j][d4 * 4];
            __half2 h0 = *reinterpret_cast<__half2*>(&r.x);
            __half2 h1 = *reinterpret_cast<__half2*>(&r.y);
            float2 f0 = __half22float2(h0);
            float2 f1 = __half22float2(h1);
            acc.x += ev * f0.x; acc.y += ev * f0.y;
            acc.z += ev * f1.x; acc.w += ev * f1.y;
            exsum += ev;
        }
        __syncthreads();
    }
    float scale = (exsum > 0.0f) ? (1.0f / exsum) : 0.0f;
    __half2 o0 = __floats2half2_rn(acc.x * scale, acc.y * scale);
    __half2 o1 = __floats2half2_rn(acc.z * scale, acc.w * scale);
    uint2 u;
    u.x = *reinterpret_cast<uint32_t*>(&o0);
    u.y = *reinterpret_cast<uint32_t*>(&o1);
    *(uint2*)(g_Sh + ((size_t)n * KK + k) * DD + d4 * 4) = u;
}

// ---------------- K5: out_gemm via tf32 mma.sync (fp16 S input) --------------
// block = (64 nodes, 1 head): C(64x64) = S_tile(64x128) @ W_tile(128x64)
#define AP 132   // A smem row stride
#define BP 68    // B smem row stride
#define SMEM_G ((64 * AP + DD * BP) * 4)
__global__ __launch_bounds__(256) void out_gemm_kernel(
    const float* __restrict__ W_enc, float* __restrict__ out) {
    extern __shared__ float smg[];
    float* As = smg;              // [64][AP]
    float* Bs = smg + 64 * AP;    // [DD][BP]

    int t = threadIdx.x;
    int n0 = blockIdx.x * 64;
    int k = blockIdx.y;

    // A tile: S rows n0..n0+63 from fp16 (cvt -> float -> tf32)
#pragma unroll
    for (int i = 0; i < 4; i++) {
        int idx = i * 256 + t;         // 1024 uint4s (8 halves each)
        int r = idx >> 4, c8 = idx & 15;
        int n = n0 + r;
        uint4 raw = make_uint4(0u, 0u, 0u, 0u);
        if (n < NN)
            raw = *(const uint4*)(g_Sh + ((size_t)n * KK + k) * DD + c8 * 8);
        __half2 ha = *reinterpret_cast<__half2*>(&raw.x);
        __half2 hb = *reinterpret_cast<__half2*>(&raw.y);
        __half2 hc = *reinterpret_cast<__half2*>(&raw.z);
        __half2 hd = *reinterpret_cast<__half2*>(&raw.w);
        float2 fa = __half22float2(ha), fb = __half22float2(hb);
        float2 fc = __half22float2(hc), fd = __half22float2(hd);
        *(float4*)(As + r * AP + c8 * 8) =
            make_float4(to_tf32(fa.x), to_tf32(fa.y), to_tf32(fb.x), to_tf32(fb.y));
        *(float4*)(As + r * AP + c8 * 8 + 4) =
            make_float4(to_tf32(fc.x), to_tf32(fc.y), to_tf32(fd.x), to_tf32(fd.y));
    }
    // B tile: W_enc[d][k*64 + h] (cvt tf32), stored [d][h]
#pragma unroll
    for (int i = 0; i < 8; i++) {
        int idx = i * 256 + t;         // 2048 float4s
        int d = idx >> 4, h4 = idx & 15;
        float4 v = *(const float4*)(W_enc + (size_t)d * KH + k * HH + h4 * 4);
        v.x = to_tf32(v.x); v.y = to_tf32(v.y);
        v.z = to_tf32(v.z); v.w = to_tf32(v.w);
        *(float4*)(Bs + d * BP + h4 * 4) = v;
    }
    __syncthreads();

    int w = t >> 5, lane = t & 31;
    int g = lane >> 2, tig = lane & 3;
    int warp_m = w >> 2, warp_n = w & 3;

    float c[2][2][4];
#pragma unroll
    for (int mi = 0; mi < 2; mi++)
#pragma unroll
        for (int j = 0; j < 2; j++)
#pragma unroll
            for (int q = 0; q < 4; q++) c[mi][j][q] = 0.0f;

    const uint32_t* Au = (const uint32_t*)As;
    const uint32_t* Bu = (const uint32_t*)Bs;

#pragma unroll 4
    for (int kc = 0; kc < 16; kc++) {
        int k0 = kc * 8;
        uint32_t a[2][4];
#pragma unroll
        for (int mi = 0; mi < 2; mi++) {
            int rb = warp_m * 32 + mi * 16;
            a[mi][0] = Au[(rb + g) * AP + k0 + tig];
            a[mi][1] = Au[(rb + g + 8) * AP + k0 + tig];
            a[mi][2] = Au[(rb + g) * AP + k0 + tig + 4];
            a[mi][3] = Au[(rb + g + 8) * AP + k0 + tig + 4];
        }
        uint32_t b[2][2];
#pragma unroll
        for (int j = 0; j < 2; j++) {
            int nb = warp_n * 16 + j * 8 + g;
            b[j][0] = Bu[(k0 + tig) * BP + nb];
            b[j][1] = Bu[(k0 + tig + 4) * BP + nb];
        }
#pragma unroll
        for (int mi = 0; mi < 2; mi++)
#pragma unroll
            for (int j = 0; j < 2; j++) mma_tf32(c[mi][j], a[mi], b[j]);
    }

#pragma unroll
    for (int mi = 0; mi < 2; mi++) {
        int row0 = n0 + warp_m * 32 + mi * 16 + g;
#pragma unroll
        for (int j = 0; j < 2; j++) {
            int col = k * HH + warp_n * 16 + j * 8 + 2 * tig;
            if (row0 < NN)
                *(float2*)(out + (size_t)row0 * KH + col) =
                    make_float2(c[mi][j][0], c[mi][j][1]);
            if (row0 + 8 < NN)
                *(float2*)(out + (size_t)(row0 + 8) * KH + col) =
                    make_float2(c[mi][j][2], c[mi][j][3]);
        }
    }
}

// ---------------- launch -----------------------------------------------------
extern "C" void kernel_launch(void* const* d_in, const int* in_sizes, int n_in,
                              void* d_out, int out_size) {
    const float* node_feat = (const float*)d_in[0];   // (N,128)
    const float* edge_feat = (const float*)d_in[1];   // (E,3,128)
    const float* W_enc     = (const float*)d_in[2];   // (128,512)
    const float* attn_l    = (const float*)d_in[3];   // (1,8,64)
    const float* W_r       = (const float*)d_in[4];   // (8,128)
    const int*   dst       = (const int*)d_in[5];     // (E,)
    float* out = (float*)d_out;                       // (N,8,64)

    cudaFuncSetAttribute(out_gemm_kernel,
                         cudaFuncAttributeMaxDynamicSharedMemorySize, SMEM_G);

    prep_hist_kernel<<<2504, 256>>>(node_feat, W_r, W_enc, attn_l, dst);
    scan_kernel<<<1, 1024>>>();
    mean_logits_fill_kernel<<<EE / 8, 256>>>(edge_feat, dst);
    aggregate_kernel<<<NN, 256>>>();
    out_gemm_kernel<<<dim3((NN + 63) / 64, KK), 256, SMEM_G>>>(W_enc, out);
}

// round 16
// speedup vs baseline: 1.0728x; 1.0314x over previous
#include <cuda_runtime.h>
#include <cuda_fp16.h>
#include <cstdint>

#define NN 20000
#define EE 320000
#define DD 128
#define KK 8
#define HH 64
#define KH 512   // K*H

// ---------------- scratch (static device arrays, zero-initialized) ----------
__device__ __half g_meanh[(size_t)EE * DD];        // 82 MB mean features (fp16)
__device__ float g_ex[(size_t)EE * KK];            // exp(logits)
__device__ float g_er[(size_t)NN * KK];            // node_feat @ W_r^T
__device__ float g_W2[KK * DD];                    // [k][d] reduced weights
__device__ __half g_Sh[(size_t)NN * KK * DD];      // aggregated, normalized (fp16)
__device__ int   g_cnt[NN];                        // zero at entry (scan re-zeroes)
__device__ int   g_off[NN + 1];
__device__ int   g_cur[NN];
__device__ int   g_list[EE];

__device__ __forceinline__ float to_tf32(float x) {
    float r;
    asm("cvt.rna.tf32.f32 %0, %1;" : "=f"(r) : "f"(x));
    return r;
}
__device__ __forceinline__ void mma_tf32(float* c, const uint32_t* a, const uint32_t* b) {
    asm volatile(
        "mma.sync.aligned.m16n8k8.row.col.f32.tf32.tf32.f32 "
        "{%0,%1,%2,%3}, {%4,%5,%6,%7}, {%8,%9}, {%0,%1,%2,%3};"
        : "+f"(c[0]), "+f"(c[1]), "+f"(c[2]), "+f"(c[3])
        : "r"(a[0]), "r"(a[1]), "r"(a[2]), "r"(a[3]), "r"(b[0]), "r"(b[1]));
}

// ---------------- K1: W2 + er + histogram (all independent) ------------------
__global__ __launch_bounds__(256) void prep_hist_kernel(
    const float* __restrict__ nf, const float* __restrict__ Wr,
    const float* __restrict__ W_enc, const float* __restrict__ attn_l,
    const int* __restrict__ dst) {
    int b = blockIdx.x;
    int t = threadIdx.x;
    if (b < 1250) {                       // histogram part
        int e = b * 256 + t;
        atomicAdd(&g_cnt[dst[e]], 1);
    }
    if (b < 4) {
        int idx = b * 256 + t;
        if (idx < KK * DD) {
            int d = idx >> 3, k = idx & 7;
            float s = 0.0f;
#pragma unroll 8
            for (int h = 0; h < HH; h++)
                s += W_enc[(size_t)d * KH + k * HH + h] * attn_l[k * HH + h];
            g_W2[k * DD + d] = s;
        }
    } else {
        int warp = (b - 4) * 8 + (t >> 5);
        int lane = t & 31;
        if (warp >= NN) return;
        float4 x = *(const float4*)(nf + (size_t)warp * DD + lane * 4);
#pragma unroll
        for (int k = 0; k < KK; k++) {
            float4 w = *(const float4*)(Wr + (size_t)k * DD + lane * 4);
            float p = x.x * w.x + x.y * w.y + x.z * w.z + x.w * w.w;
#pragma unroll
            for (int off = 16; off > 0; off >>= 1)
                p += __shfl_xor_sync(0xffffffffu, p, off);
            if (lane == 0) g_er[(size_t)warp * KK + k] = p;
        }
    }
}

// ---------------- K2: scan (single block) ------------------------------------
__global__ void scan_kernel() {   // 1024 threads, 20 counts each
    __shared__ int part[1024];
    int t = threadIdx.x;
    int base = t * 20;
    int loc[20];
    int s = 0;
#pragma unroll
    for (int i = 0; i < 20; i++) {
        int idx = base + i;
        int c = (idx < NN) ? g_cnt[idx] : 0;
        loc[i] = s;
        s += c;
    }
    part[t] = s;
    __syncthreads();
    for (int off = 1; off < 1024; off <<= 1) {
        int v = (t >= off) ? part[t - off] : 0;
        __syncthreads();
        part[t] += v;
        __syncthreads();
    }
    int excl = (t == 0) ? 0 : part[t - 1];
#pragma unroll
    for (int i = 0; i < 20; i++) {
        int idx = base + i;
        if (idx < NN) {
            g_off[idx] = excl + loc[i];
            g_cur[idx] = excl + loc[i];
            g_cnt[idx] = 0;            // leave zeroed for next launch call
        }
    }
    if (t == 1023) g_off[NN] = part[1023];
}

// ---------------- K3: mean + logits + exp (2 edges per warp), + CSR fill -----
// EE/16 = 20000 blocks x 256 threads; warp w handles edges 16b + 2w, +1.
__global__ __launch_bounds__(256) void mean_logits_fill_kernel(
    const float* __restrict__ ef, const int* __restrict__ dst) {
    __shared__ float w2s[KK * DD];
    int t = threadIdx.x;

    if (blockIdx.x < 1250) {              // fill part (needs scan done: K2)
        int e = blockIdx.x * 256 + t;
        int p = atomicAdd(&g_cur[dst[e]], 1);
        g_list[p] = e;
    }

    for (int i = t; i < KK * DD; i += 256) w2s[i] = g_W2[i];
    __syncthreads();

    int e0 = blockIdx.x * 16 + (t >> 5) * 2;   // first of 2 edges
    int lane = t & 31;

    // issue all 6 loads up front (MLP=6)
    size_t base0 = (size_t)e0 * 3 * DD + lane * 4;
    size_t base1 = base0 + 3 * DD;
    float4 a0 = *(const float4*)(ef + base0);
    float4 b0 = *(const float4*)(ef + base0 + DD);
    float4 c0 = *(const float4*)(ef + base0 + 2 * DD);
    float4 a1 = *(const float4*)(ef + base1);
    float4 b1 = *(const float4*)(ef + base1 + DD);
    float4 c1 = *(const float4*)(ef + base1 + 2 * DD);

    const float s = 1.0f / 3.0f;
    float4 m0, m1;
    m0.x = (a0.x + b0.x + c0.x) * s; m0.y = (a0.y + b0.y + c0.y) * s;
    m0.z = (a0.z + b0.z + c0.z) * s; m0.w = (a0.w + b0.w + c0.w) * s;
    m1.x = (a1.x + b1.x + c1.x) * s; m1.y = (a1.y + b1.y + c1.y) * s;
    m1.z = (a1.z + b1.z + c1.z) * s; m1.w = (a1.w + b1.w + c1.w) * s;

    {
        __half2 h0 = __floats2half2_rn(m0.x, m0.y);
        __half2 h1 = __floats2half2_rn(m0.z, m0.w);
        uint2 u;
        u.x = *reinterpret_cast<uint32_t*>(&h0);
        u.y = *reinterpret_cast<uint32_t*>(&h1);
        *(uint2*)(g_meanh + (size_t)e0 * DD + lane * 4) = u;
        __half2 h2 = __floats2half2_rn(m1.x, m1.y);
        __half2 h3 = __floats2half2_rn(m1.z, m1.w);
        uint2 v;
        v.x = *reinterpret_cast<uint32_t*>(&h2);
        v.y = *reinterpret_cast<uint32_t*>(&h3);
        *(uint2*)(g_meanh + (size_t)(e0 + 1) * DD + lane * 4) = v;
    }

    float pk0[KK], pk1[KK];
#pragma unroll
    for (int k = 0; k < KK; k++) {
        float4 w = *(const float4*)(w2s + k * DD + lane * 4);
        pk0[k] = m0.x * w.x + m0.y * w.y + m0.z * w.z + m0.w * w.w;
        pk1[k] = m1.x * w.x + m1.y * w.y + m1.z * w.z + m1.w * w.w;
    }
    // fold reduction for both edges (interleaved): 8 vals -> 1/lane in 9 SHFLs
    float v40[4], v41[4];
#pragma unroll
    for (int i = 0; i < 4; i++) {
        float s0 = (lane & 16) ? pk0[i] : pk0[i + 4];
        float s1 = (lane & 16) ? pk1[i] : pk1[i + 4];
        float r0 = __shfl_xor_sync(0xffffffffu, s0, 16);
        float r1 = __shfl_xor_sync(0xffffffffu, s1, 16);
        v40[i] = ((lane & 16) ? pk0[i + 4] : pk0[i]) + r0;
        v41[i] = ((lane & 16) ? pk1[i + 4] : pk1[i]) + r1;
    }
    float v20[2], v21[2];
#pragma unroll
    for (int i = 0; i < 2; i++) {
        float s0 = (lane & 8) ? v40[i] : v40[i + 2];
        float s1 = (lane & 8) ? v41[i] : v41[i + 2];
        float r0 = __shfl_xor_sync(0xffffffffu, s0, 8);
        float r1 = __shfl_xor_sync(0xffffffffu, s1, 8);
        v20[i] = ((lane & 8) ? v40[i + 2] : v40[i]) + r0;
        v21[i] = ((lane & 8) ? v41[i + 2] : v41[i]) + r1;
    }
    {
        float s0 = (lane & 4) ? v20[0] : v20[1];
        float s1 = (lane & 4) ? v21[0] : v21[1];
        float r0 = __shfl_xor_sync(0xffffffffu, s0, 4);
        float r1 = __shfl_xor_sync(0xffffffffu, s1, 4);
        v20[0] = ((lane & 4) ? v20[1] : v20[0]) + r0;
        v21[0] = ((lane & 4) ? v21[1] : v21[0]) + r1;
    }
    v20[0] += __shfl_xor_sync(0xffffffffu, v20[0], 1);
    v21[0] += __shfl_xor_sync(0xffffffffu, v21[0], 1);
    v20[0] += __shfl_xor_sync(0xffffffffu, v20[0], 2);
    v21[0] += __shfl_xor_sync(0xffffffffu, v21[0], 2);
    // lanes with lane&3==0 hold el for head k = lane>>2

    int d0 = dst[e0];
    int d1 = dst[e0 + 1];
    if ((lane & 3) == 0) {
        int k = lane >> 2;
        float v = v20[0] + g_er[(size_t)d0 * KK + k];
        v = (v > 0.0f) ? v : 0.01f * v;
        g_ex[(size_t)e0 * KK + k] = expf(v);
        float u = v21[0] + g_er[(size_t)d1 * KK + k];
        u = (u > 0.0f) ? u : 0.01f * u;
        g_ex[(size_t)(e0 + 1) * KK + k] = expf(u);
    }
}

// ---------------- K4: per-node gather-aggregate (staged; fp16 S output) ------
#define BATCH 32
__global__ __launch_bounds__(256) void aggregate_kernel() {
    __shared__ __half msh[BATCH][DD];    // 8 KB
    __shared__ float exs[BATCH][KK];     // 1 KB
    int n = blockIdx.x;
    int t = threadIdx.x;
    int k = t >> 5, d4 = t & 31;
    int beg = g_off[n], end = g_off[n + 1];

    float4 acc = make_float4(0.f, 0.f, 0.f, 0.f);
    float exsum = 0.0f;

    for (int p0 = beg; p0 < end; p0 += BATCH) {
        int nb = end - p0;
        if (nb > BATCH) nb = BATCH;
        for (int i = t; i < nb * 16; i += 256) {
            int j = i >> 4, c8 = i & 15;
            int e = g_list[p0 + j];
            *(uint4*)&msh[j][c8 * 8] =
                *(const uint4*)(g_meanh + (size_t)e * DD + c8 * 8);
        }
        if (t < nb * KK) {
            int j = t >> 3, kk = t & 7;
            int e = g_list[p0 + j];
            exs[j][kk] = g_ex[(size_t)e * KK + kk];
        }
        __syncthreads();
#pragma unroll 4
        for (int j = 0; j < nb; j++) {
            float ev = exs[j][k];
            uint2 r = *(const uint2*)&msh[j][d4 * 4];
            __half2 h0 = *reinterpret_cast<__half2*>(&r.x);
            __half2 h1 = *reinterpret_cast<__half2*>(&r.y);
            float2 f0 = __half22float2(h0);
            float2 f1 = __half22float2(h1);
            acc.x += ev * f0.x; acc.y += ev * f0.y;
            acc.z += ev * f1.x; acc.w += ev * f1.y;
            exsum += ev;
        }
        __syncthreads();
    }
    float scale = (exsum > 0.0f) ? (1.0f / exsum) : 0.0f;
    __half2 o0 = __floats2half2_rn(acc.x * scale, acc.y * scale);
    __half2 o1 = __floats2half2_rn(acc.z * scale, acc.w * scale);
    uint2 u;
    u.x = *reinterpret_cast<uint32_t*>(&o0);
    u.y = *reinterpret_cast<uint32_t*>(&o1);
    *(uint2*)(g_Sh + ((size_t)n * KK + k) * DD + d4 * 4) = u;
}

// ---------------- K5: out_gemm via tf32 mma.sync (fp16 S input) --------------
#define AP 132   // A smem row stride
#define BP 68    // B smem row stride
#define SMEM_G ((64 * AP + DD * BP) * 4)
__global__ __launch_bounds__(256) void out_gemm_kernel(
    const float* __restrict__ W_enc, float* __restrict__ out) {
    extern __shared__ float smg[];
    float* As = smg;              // [64][AP]
    float* Bs = smg + 64 * AP;    // [DD][BP]

    int t = threadIdx.x;
    int n0 = blockIdx.x * 64;
    int k = blockIdx.y;

#pragma unroll
    for (int i = 0; i < 4; i++) {
        int idx = i * 256 + t;         // 1024 uint4s (8 halves each)
        int r = idx >> 4, c8 = idx & 15;
        int n = n0 + r;
        uint4 raw = make_uint4(0u, 0u, 0u, 0u);
        if (n < NN)
            raw = *(const uint4*)(g_Sh + ((size_t)n * KK + k) * DD + c8 * 8);
        __half2 ha = *reinterpret_cast<__half2*>(&raw.x);
        __half2 hb = *reinterpret_cast<__half2*>(&raw.y);
        __half2 hc = *reinterpret_cast<__half2*>(&raw.z);
        __half2 hd = *reinterpret_cast<__half2*>(&raw.w);
        float2 fa = __half22float2(ha), fb = __half22float2(hb);
        float2 fc = __half22float2(hc), fd = __half22float2(hd);
        *(float4*)(As + r * AP + c8 * 8) =
            make_float4(to_tf32(fa.x), to_tf32(fa.y), to_tf32(fb.x), to_tf32(fb.y));
        *(float4*)(As + r * AP + c8 * 8 + 4) =
            make_float4(to_tf32(fc.x), to_tf32(fc.y), to_tf32(fd.x), to_tf32(fd.y));
    }
#pragma unroll
    for (int i = 0; i < 8; i++) {
        int idx = i * 256 + t;         // 2048 float4s
        int d = idx >> 4, h4 = idx & 15;
        float4 v = *(const float4*)(W_enc + (size_t)d * KH + k * HH + h4 * 4);
        v.x = to_tf32(v.x); v.y = to_tf32(v.y);
        v.z = to_tf32(v.z); v.w = to_tf32(v.w);
        *(float4*)(Bs + d * BP + h4 * 4) = v;
    }
    __syncthreads();

    int w = t >> 5, lane = t & 31;
    int g = lane >> 2, tig = lane & 3;
    int warp_m = w >> 2, warp_n = w & 3;

    float c[2][2][4];
#pragma unroll
    for (int mi = 0; mi < 2; mi++)
#pragma unroll
        for (int j = 0; j < 2; j++)
#pragma unroll
            for (int q = 0; q < 4; q++) c[mi][j][q] = 0.0f;

    const uint32_t* Au = (const uint32_t*)As;
    const uint32_t* Bu = (const uint32_t*)Bs;

#pragma unroll 4
    for (int kc = 0; kc < 16; kc++) {
        int k0 = kc * 8;
        uint32_t a[2][4];
#pragma unroll
        for (int mi = 0; mi < 2; mi++) {
            int rb = warp_m * 32 + mi * 16;
            a[mi][0] = Au[(rb + g) * AP + k0 + tig];
            a[mi][1] = Au[(rb + g + 8) * AP + k0 + tig];
            a[mi][2] = Au[(rb + g) * AP + k0 + tig + 4];
            a[mi][3] = Au[(rb + g + 8) * AP + k0 + tig + 4];
        }
        uint32_t b[2][2];
#pragma unroll
        for (int j = 0; j < 2; j++) {
            int nb = warp_n * 16 + j * 8 + g;
            b[j][0] = Bu[(k0 + tig) * BP + nb];
            b[j][1] = Bu[(k0 + tig + 4) * BP + nb];
        }
#pragma unroll
        for (int mi = 0; mi < 2; mi++)
#pragma unroll
            for (int j = 0; j < 2; j++) mma_tf32(c[mi][j], a[mi], b[j]);
    }

#pragma unroll
    for (int mi = 0; mi < 2; mi++) {
        int row0 = n0 + warp_m * 32 + mi * 16 + g;
#pragma unroll
        for (int j = 0; j < 2; j++) {
            int col = k * HH + warp_n * 16 + j * 8 + 2 * tig;
            if (row0 < NN)
                *(float2*)(out + (size_t)row0 * KH + col) =
                    make_float2(c[mi][j][0], c[mi][j][1]);
            if (row0 + 8 < NN)
                *(float2*)(out + (size_t)(row0 + 8) * KH + col) =
                    make_float2(c[mi][j][2], c[mi][j][3]);
        }
    }
}

// ---------------- launch -----------------------------------------------------
extern "C" void kernel_launch(void* const* d_in, const int* in_sizes, int n_in,
                              void* d_out, int out_size) {
    const float* node_feat = (const float*)d_in[0];   // (N,128)
    const float* edge_feat = (const float*)d_in[1];   // (E,3,128)
    const float* W_enc     = (const float*)d_in[2];   // (128,512)
    const float* attn_l    = (const float*)d_in[3];   // (1,8,64)
    const float* W_r       = (const float*)d_in[4];   // (8,128)
    const int*   dst       = (const int*)d_in[5];     // (E,)
    float* out = (float*)d_out;                       // (N,8,64)

    cudaFuncSetAttribute(out_gemm_kernel,
                         cudaFuncAttributeMaxDynamicSharedMemorySize, SMEM_G);

    prep_hist_kernel<<<2504, 256>>>(node_feat, W_r, W_enc, attn_l, dst);
    scan_kernel<<<1, 1024>>>();
    mean_logits_fill_kernel<<<EE / 16, 256>>>(edge_feat, dst);
    aggregate_kernel<<<NN, 256>>>();
    out_gemm_kernel<<<dim3((NN + 63) / 64, KK), 256, SMEM_G>>>(W_enc, out);
}